// round 1
// baseline (speedup 1.0000x reference)
#include <cuda_runtime.h>
#include <cstddef>

// IntegerNeuron: T-step integrate-and-fire scan over [T,B,C,H,W] fp32.
// Pure HBM-streaming kernel: each thread owns 4 contiguous spatial elements
// (one float4), loads all 8 T-slices up front (MLP=8), runs the recurrence
// in registers, streams out 8 spike float4s.

#define T_STEPS 8
#define B_DIM   32
#define C_DIM   256
#define H_DIM   32
#define W_DIM   32
#define EPS_F   1e-12f

// elements per T-slice = B*C*H*W = 8,388,608 ; in float4 units:
#define N4 (B_DIM * C_DIM * H_DIM * W_DIM / 4)   // 2,097,152

__global__ __launch_bounds__(256) void integer_neuron_kernel(
    const float* __restrict__ x_accum,     // [T,B,C,H,W]
    const float* __restrict__ prev_scale,  // [C]
    const float* __restrict__ prev_bias,   // [C]
    const float* __restrict__ vth,         // [C]
    const float* __restrict__ tau_ptr,     // [1]
    const int*   __restrict__ is_first,    // [1] (int32 scalar)
    float*       __restrict__ out)         // [T,B,C,H,W]
{
    int idx = blockIdx.x * blockDim.x + threadIdx.x;   // float4 index within a T-slice
    if (idx >= N4) return;

    // element index of first lane of this float4; channel = (e / (H*W)) % C
    int e = idx << 2;
    int c = (e >> 10) & (C_DIM - 1);   // H*W = 1024, C = 256

    float tau  = __ldg(tau_ptr);
    float sc   = __ldg(prev_scale + c);
    float inv  = tau / (sc + EPS_F);
    float bias_scaled = nearbyintf(__ldg(prev_bias + c) * inv);  // half-to-even, matches jnp.round
    float vth_scaled  = nearbyintf(__ldg(vth + c) * inv);
    float drive_mul   = (__ldg(is_first) != 0) ? 1.0f : tau;

    const float4* __restrict__ x4 = (const float4*)x_accum;
    float4* __restrict__ o4 = (float4*)out;

    // Front-load all 8 independent T-slice loads (MLP=8 per thread).
    float4 xs[T_STEPS];
#pragma unroll
    for (int t = 0; t < T_STEPS; t++)
        xs[t] = x4[(size_t)t * N4 + idx];

    float4 mem = make_float4(0.f, 0.f, 0.f, 0.f);

#pragma unroll
    for (int t = 0; t < T_STEPS; t++) {
        float4 xt = xs[t];
        // drive = x * tau (separate rounding step, matching reference),
        // then mem = (mem + drive) + bias_scaled (reference eval order)
        float dx = xt.x * drive_mul;
        float dy = xt.y * drive_mul;
        float dz = xt.z * drive_mul;
        float dw = xt.w * drive_mul;

        mem.x = (mem.x + dx) + bias_scaled;
        mem.y = (mem.y + dy) + bias_scaled;
        mem.z = (mem.z + dz) + bias_scaled;
        mem.w = (mem.w + dw) + bias_scaled;

        float4 sp;
        sp.x = (mem.x >= vth_scaled) ? 1.0f : 0.0f;
        sp.y = (mem.y >= vth_scaled) ? 1.0f : 0.0f;
        sp.z = (mem.z >= vth_scaled) ? 1.0f : 0.0f;
        sp.w = (mem.w >= vth_scaled) ? 1.0f : 0.0f;

        mem.x -= sp.x * vth_scaled;
        mem.y -= sp.y * vth_scaled;
        mem.z -= sp.z * vth_scaled;
        mem.w -= sp.w * vth_scaled;

        o4[(size_t)t * N4 + idx] = sp;
    }
}

extern "C" void kernel_launch(void* const* d_in, const int* in_sizes, int n_in,
                              void* d_out, int out_size)
{
    const float* x_accum    = (const float*)d_in[0];
    const float* prev_scale = (const float*)d_in[1];
    const float* prev_bias  = (const float*)d_in[2];
    const float* vth        = (const float*)d_in[3];
    const float* tau        = (const float*)d_in[4];
    const int*   is_first   = (const int*)d_in[5];
    float* out = (float*)d_out;

    const int threads = 256;
    const int blocks  = (N4 + threads - 1) / threads;  // 8192
    integer_neuron_kernel<<<blocks, threads>>>(
        x_accum, prev_scale, prev_bias, vth, tau, is_first, out);
}

// round 2
// speedup vs baseline: 1.0019x; 1.0019x over previous
#include <cuda_runtime.h>
#include <cstddef>

// IntegerNeuron: T-step integrate-and-fire scan over [T,B,C,H,W] fp32.
// Pure HBM streaming (512 MiB compulsory traffic). Touch-once data:
// streaming cache hints (__ldcs/__stcs), 2x4 split load batching to cap
// per-CTA L1tex queue depth, no tail branch (grid divides exactly).

#define T_STEPS 8
#define B_DIM   32
#define C_DIM   256
#define H_DIM   32
#define W_DIM   32
#define EPS_F   1e-12f

// float4 elements per T-slice
#define N4 (B_DIM * C_DIM * H_DIM * W_DIM / 4)   // 2,097,152  (= 8192 blocks * 256 thr)

__global__ __launch_bounds__(256) void integer_neuron_kernel(
    const float4* __restrict__ x4,         // [T,B,C,H,W] viewed as float4
    const float*  __restrict__ prev_scale, // [C]
    const float*  __restrict__ prev_bias,  // [C]
    const float*  __restrict__ vth,        // [C]
    const float*  __restrict__ tau_ptr,    // [1]
    const int*    __restrict__ is_first,   // [1]
    float4*       __restrict__ o4)         // [T,B,C,H,W] viewed as float4
{
    const int idx = blockIdx.x * blockDim.x + threadIdx.x;  // exact: no tail

    // channel of this float4 group: element = idx*4, H*W = 1024, C = 256
    const int c = ((idx << 2) >> 10) & (C_DIM - 1);

    const float tau = __ldg(tau_ptr);
    const float inv = tau / (__ldg(prev_scale + c) + EPS_F);
    const float bias_scaled = nearbyintf(__ldg(prev_bias + c) * inv); // half-to-even = jnp.round
    const float vth_scaled  = nearbyintf(__ldg(vth + c) * inv);
    const float drive_mul   = (__ldg(is_first) != 0) ? 1.0f : tau;

    float4 xs[T_STEPS];
    // batch 1: T-slices 0..3 (MLP=4)
#pragma unroll
    for (int t = 0; t < 4; t++)
        xs[t] = __ldcs(x4 + (size_t)t * N4 + idx);

    float4 mem = make_float4(0.f, 0.f, 0.f, 0.f);

#pragma unroll
    for (int t = 0; t < T_STEPS; t++) {
        if (t == 4) {
            // batch 2: T-slices 4..7, overlapped with first-half compute/stores
#pragma unroll
            for (int u = 4; u < T_STEPS; u++)
                xs[u] = __ldcs(x4 + (size_t)u * N4 + idx);
        }
        const float4 xt = xs[t];

        // reference eval order: mem = (mem + x*tau) + bias_scaled
        mem.x = (mem.x + xt.x * drive_mul) + bias_scaled;
        mem.y = (mem.y + xt.y * drive_mul) + bias_scaled;
        mem.z = (mem.z + xt.z * drive_mul) + bias_scaled;
        mem.w = (mem.w + xt.w * drive_mul) + bias_scaled;

        float4 sp;
        sp.x = (mem.x >= vth_scaled) ? 1.0f : 0.0f;
        sp.y = (mem.y >= vth_scaled) ? 1.0f : 0.0f;
        sp.z = (mem.z >= vth_scaled) ? 1.0f : 0.0f;
        sp.w = (mem.w >= vth_scaled) ? 1.0f : 0.0f;

        mem.x -= sp.x * vth_scaled;
        mem.y -= sp.y * vth_scaled;
        mem.z -= sp.z * vth_scaled;
        mem.w -= sp.w * vth_scaled;

        __stcs(o4 + (size_t)t * N4 + idx, sp);
    }
}

extern "C" void kernel_launch(void* const* d_in, const int* in_sizes, int n_in,
                              void* d_out, int out_size)
{
    const float4* x_accum    = (const float4*)d_in[0];
    const float*  prev_scale = (const float*)d_in[1];
    const float*  prev_bias  = (const float*)d_in[2];
    const float*  vth        = (const float*)d_in[3];
    const float*  tau        = (const float*)d_in[4];
    const int*    is_first   = (const int*)d_in[5];
    float4* out = (float4*)d_out;

    const int threads = 256;
    const int blocks  = N4 / threads;  // 8192, exact
    integer_neuron_kernel<<<blocks, threads>>>(
        x_accum, prev_scale, prev_bias, vth, tau, is_first, out);
}